// round 1
// baseline (speedup 1.0000x reference)
#include <cuda_runtime.h>
#include <math.h>
#include <stdint.h>

// Problem constants (fixed shapes)
#define NB   32
#define SEQ  512
#define EMB  128
#define BSE  (NB*SEQ*EMB)

// ---------------------------------------------------------------------------
// Scratch (static device arrays; no allocations allowed)
// ---------------------------------------------------------------------------
__device__ float g_Q [BSE];
__device__ float g_K [BSE];
__device__ float g_V [BSE];
__device__ float g_Ke[BSE];
__device__ float g_Ve[BSE];
__device__ float g_O1[BSE];
__device__ float g_O2[BSE];
__device__ float g_MH[BSE];

enum { JOB_Q = 0, JOB_K, JOB_V, JOB_KE, JOB_VE, JOB_MH };

// dynamic smem sizes
constexpr int GEMM_SMEM  = 64*132*4 + 128*32*16;              // 99328 B
constexpr int ATTN_SMEM  = (64*128 + 64*128 + 64*64) * 4;     // 81920 B
constexpr int FINAL_SMEM = (32*132 + 64*132 + 32*516) * 4;    // 116736 B

// ---------------------------------------------------------------------------
// Multi-pair GEMM: Y[16384,128] = sum_p Xp[16384,128] @ Wp[128,128] (+bias0+bias1)
// Block: 64 rows x 128 cols, 256 threads, each thread 2 rows x 16 cols.
// ---------------------------------------------------------------------------
__global__ __launch_bounds__(256)
void gemm128(int job,
             const float* __restrict__ x0, const float* __restrict__ x1,
             const float* __restrict__ x2, const float* __restrict__ x3,
             const float* __restrict__ w0, const float* __restrict__ w1,
             const float* __restrict__ w2, const float* __restrict__ w3,
             const float* __restrict__ bias0, const float* __restrict__ bias1)
{
    extern __shared__ float sm[];
    float*  sX = sm;                         // [64][132]
    float4* sW = (float4*)(sm + 64*132);     // [128][32] float4

    const float* Xs[4] = {x0, x1, x2, x3};
    const float* Ws[4] = {w0, w1, w2, w3};
    float* Y; int npair;
    switch (job) {
        case JOB_Q:  Y = g_Q;  npair = 4; break;
        case JOB_K:  Y = g_K;  npair = 1; break;
        case JOB_V:  Y = g_V;  npair = 1; break;
        case JOB_KE: Y = g_Ke; npair = 1; break;
        case JOB_VE: Y = g_Ve; npair = 1; break;
        default:     Y = g_MH; npair = 2; Xs[0] = g_O1; Xs[1] = g_O2; break;
    }

    const int tid  = threadIdx.x;
    const int row0 = blockIdx.x * 64;
    const int r    = tid >> 3;   // 0..31
    const int cg   = tid & 7;    // cols 4*(cg+8j)+0..3

    float4 acc[2][4];
    #pragma unroll
    for (int a = 0; a < 2; ++a)
        #pragma unroll
        for (int j = 0; j < 4; ++j) acc[a][j] = make_float4(0.f, 0.f, 0.f, 0.f);

    for (int p = 0; p < npair; ++p) {
        const float4* Wsrc = (const float4*)Ws[p];
        #pragma unroll
        for (int i = 0; i < 16; ++i) sW[tid + i*256] = Wsrc[tid + i*256];
        const float4* Xsrc = (const float4*)(Xs[p] + (size_t)row0 * EMB);
        #pragma unroll
        for (int i = 0; i < 8; ++i) {
            int idx = tid + i*256;                       // 0..2047
            float4 v = Xsrc[idx];
            ((float4*)(sX + (idx >> 5) * 132))[idx & 31] = v;
        }
        __syncthreads();

        #pragma unroll 8
        for (int k = 0; k < 128; ++k) {
            float xa = sX[r*132 + k];
            float xb = sX[(r+32)*132 + k];
            #pragma unroll
            for (int j = 0; j < 4; ++j) {
                float4 w = sW[k*32 + cg + 8*j];
                acc[0][j].x = fmaf(xa, w.x, acc[0][j].x);
                acc[0][j].y = fmaf(xa, w.y, acc[0][j].y);
                acc[0][j].z = fmaf(xa, w.z, acc[0][j].z);
                acc[0][j].w = fmaf(xa, w.w, acc[0][j].w);
                acc[1][j].x = fmaf(xb, w.x, acc[1][j].x);
                acc[1][j].y = fmaf(xb, w.y, acc[1][j].y);
                acc[1][j].z = fmaf(xb, w.z, acc[1][j].z);
                acc[1][j].w = fmaf(xb, w.w, acc[1][j].w);
            }
        }
        __syncthreads();
    }

    float4 bv[4];
    #pragma unroll
    for (int j = 0; j < 4; ++j) bv[j] = make_float4(0.f, 0.f, 0.f, 0.f);
    if (bias0 != nullptr) {
        #pragma unroll
        for (int j = 0; j < 4; ++j) {
            float4 a = ((const float4*)bias0)[cg + 8*j];
            float4 b = ((const float4*)bias1)[cg + 8*j];
            bv[j] = make_float4(a.x + b.x, a.y + b.y, a.z + b.z, a.w + b.w);
        }
    }

    #pragma unroll
    for (int a = 0; a < 2; ++a) {
        size_t row = (size_t)row0 + r + 32*a;
        float4* yr = (float4*)(Y + row * EMB);
        #pragma unroll
        for (int j = 0; j < 4; ++j) {
            float4 o = acc[a][j];
            o.x += bv[j].x; o.y += bv[j].y; o.z += bv[j].z; o.w += bv[j].w;
            yr[cg + 8*j] = o;
        }
    }
}

// ---------------------------------------------------------------------------
// Dual-MHA flash-style kernel. grid = (8 qtiles, 32 batches, 2 mhas), 256 thr.
// Thread mapping: hp = tid>>6 (head pair), ql = tid&63 (query in tile).
// Warp = 32 consecutive ql with same hp -> K/V smem reads are pure broadcasts.
// Mask stored transposed in smem -> conflict-free per-key read.
// ---------------------------------------------------------------------------
__global__ __launch_bounds__(256, 2)
void attn_kernel(const float* __restrict__ mask)
{
    extern __shared__ float sm[];
    float* sK  = sm;                 // [64][128]
    float* sV  = sm + 64*128;        // [64][128]
    float* sMT = sV + 64*128;        // [64 keys][64 queries]

    const int tid = threadIdx.x;
    const int b   = blockIdx.y;
    const int q0  = blockIdx.x * 64;
    const int mha = blockIdx.z;

    const float* Kg = mha ? g_Ke : g_K;
    const float* Vg = mha ? g_Ve : g_V;
    float*       Og = mha ? g_O2 : g_O1;

    const int hp = tid >> 6;   // 0..3 -> heads 2hp, 2hp+1 -> cols hp*32 + hh*16
    const int ql = tid & 63;

    // load q (scaled by 1/sqrt(16) = 0.25 to fold the score scale)
    float4 qreg[2][4];
    {
        const float4* qsrc = (const float4*)(g_Q + ((size_t)b*SEQ + q0 + ql)*EMB + hp*32);
        #pragma unroll
        for (int hh = 0; hh < 2; ++hh)
            #pragma unroll
            for (int i = 0; i < 4; ++i) {
                float4 v = qsrc[hh*4 + i];
                v.x *= 0.25f; v.y *= 0.25f; v.z *= 0.25f; v.w *= 0.25f;
                qreg[hh][i] = v;
            }
    }

    float  mrun[2] = {-1e30f, -1e30f};
    float  lrun[2] = {0.f, 0.f};
    float4 acc[2][4];
    #pragma unroll
    for (int hh = 0; hh < 2; ++hh)
        #pragma unroll
        for (int i = 0; i < 4; ++i) acc[hh][i] = make_float4(0.f, 0.f, 0.f, 0.f);

    const float* Kb = Kg + (size_t)b*SEQ*EMB;
    const float* Vb = Vg + (size_t)b*SEQ*EMB;
    const float* Mb = mask + ((size_t)b*SEQ + q0)*SEQ;

    for (int kt = 0; kt < 8; ++kt) {
        const int k0 = kt * 64;
        // --- load K, V tiles (coalesced float4) ---
        {
            const float4* src = (const float4*)(Kb + (size_t)k0*EMB);
            float4* dst = (float4*)sK;
            #pragma unroll
            for (int i = 0; i < 8; ++i) dst[tid + i*256] = src[tid + i*256];
            src = (const float4*)(Vb + (size_t)k0*EMB);
            dst = (float4*)sV;
            #pragma unroll
            for (int i = 0; i < 8; ++i) dst[tid + i*256] = src[tid + i*256];
            // --- mask transpose: sMT[key][query] ---
            const int mq = tid >> 2;       // 0..63 query
            const int mg = tid & 3;        // 16 keys each
            const float4* msrc = (const float4*)(Mb + (size_t)mq*SEQ + k0 + mg*16);
            #pragma unroll
            for (int i = 0; i < 4; ++i) {
                float4 v = msrc[i];
                int j = mg*16 + i*4;
                sMT[(j+0)*64 + mq] = v.x;
                sMT[(j+1)*64 + mq] = v.y;
                sMT[(j+2)*64 + mq] = v.z;
                sMT[(j+3)*64 + mq] = v.w;
            }
        }
        __syncthreads();

        for (int j = 0; j < 64; ++j) {
            const float  mk   = sMT[j*64 + ql];
            const float4* krow = (const float4*)(sK + j*EMB + hp*32);
            const float4* vrow = (const float4*)(sV + j*EMB + hp*32);
            #pragma unroll
            for (int hh = 0; hh < 2; ++hh) {
                float4 ka = krow[hh*4+0], kb2 = krow[hh*4+1], kc = krow[hh*4+2], kd = krow[hh*4+3];
                float s =
                    qreg[hh][0].x*ka.x  + qreg[hh][0].y*ka.y  + qreg[hh][0].z*ka.z  + qreg[hh][0].w*ka.w +
                    qreg[hh][1].x*kb2.x + qreg[hh][1].y*kb2.y + qreg[hh][1].z*kb2.z + qreg[hh][1].w*kb2.w +
                    qreg[hh][2].x*kc.x  + qreg[hh][2].y*kc.y  + qreg[hh][2].z*kc.z  + qreg[hh][2].w*kc.w +
                    qreg[hh][3].x*kd.x  + qreg[hh][3].y*kd.y  + qreg[hh][3].z*kd.z  + qreg[hh][3].w*kd.w;
                s += mk;
                float4 va = vrow[hh*4+0], vb2 = vrow[hh*4+1], vc = vrow[hh*4+2], vd = vrow[hh*4+3];
                if (s <= mrun[hh]) {
                    float e = __expf(s - mrun[hh]);
                    lrun[hh] += e;
                    acc[hh][0].x += e*va.x;  acc[hh][0].y += e*va.y;  acc[hh][0].z += e*va.z;  acc[hh][0].w += e*va.w;
                    acc[hh][1].x += e*vb2.x; acc[hh][1].y += e*vb2.y; acc[hh][1].z += e*vb2.z; acc[hh][1].w += e*vb2.w;
                    acc[hh][2].x += e*vc.x;  acc[hh][2].y += e*vc.y;  acc[hh][2].z += e*vc.z;  acc[hh][2].w += e*vc.w;
                    acc[hh][3].x += e*vd.x;  acc[hh][3].y += e*vd.y;  acc[hh][3].z += e*vd.z;  acc[hh][3].w += e*vd.w;
                } else {
                    float c = __expf(mrun[hh] - s);
                    mrun[hh] = s;
                    lrun[hh] = fmaf(lrun[hh], c, 1.0f);
                    acc[hh][0].x = fmaf(acc[hh][0].x, c, va.x);  acc[hh][0].y = fmaf(acc[hh][0].y, c, va.y);
                    acc[hh][0].z = fmaf(acc[hh][0].z, c, va.z);  acc[hh][0].w = fmaf(acc[hh][0].w, c, va.w);
                    acc[hh][1].x = fmaf(acc[hh][1].x, c, vb2.x); acc[hh][1].y = fmaf(acc[hh][1].y, c, vb2.y);
                    acc[hh][1].z = fmaf(acc[hh][1].z, c, vb2.z); acc[hh][1].w = fmaf(acc[hh][1].w, c, vb2.w);
                    acc[hh][2].x = fmaf(acc[hh][2].x, c, vc.x);  acc[hh][2].y = fmaf(acc[hh][2].y, c, vc.y);
                    acc[hh][2].z = fmaf(acc[hh][2].z, c, vc.z);  acc[hh][2].w = fmaf(acc[hh][2].w, c, vc.w);
                    acc[hh][3].x = fmaf(acc[hh][3].x, c, vd.x);  acc[hh][3].y = fmaf(acc[hh][3].y, c, vd.y);
                    acc[hh][3].z = fmaf(acc[hh][3].z, c, vd.z);  acc[hh][3].w = fmaf(acc[hh][3].w, c, vd.w);
                }
            }
        }
        __syncthreads();
    }

    // write out: out[b][q0+ql][hp*32 + hh*16 + i] = acc / l
    float4* od = (float4*)(Og + ((size_t)b*SEQ + q0 + ql)*EMB + hp*32);
    #pragma unroll
    for (int hh = 0; hh < 2; ++hh) {
        float inv = 1.0f / lrun[hh];
        #pragma unroll
        for (int i = 0; i < 4; ++i) {
            float4 o = acc[hh][i];
            o.x *= inv; o.y *= inv; o.z *= inv; o.w *= inv;
            od[hh*4 + i] = o;
        }
    }
}

// ---------------------------------------------------------------------------
// Final: logits = 10*tanh((MH @ (nodes+graph)^T)/sqrt(128)) + mask; softmax(n).
// grid = (16 qtiles of 32, 32 batches), 256 threads.
// ---------------------------------------------------------------------------
__global__ __launch_bounds__(256)
void final_kernel(const float* __restrict__ nodes, const float* __restrict__ graph,
                  const float* __restrict__ mask, float* __restrict__ out)
{
    extern __shared__ float sm[];
    float* sMH  = sm;               // [32][132]
    float* sShk = sMH + 32*132;     // [64][132]
    float* sLg  = sShk + 64*132;    // [32][516]

    const int tid = threadIdx.x;
    const int b   = blockIdx.y;
    const int q0  = blockIdx.x * 32;

    // load MH tile
    {
        const float4* msrc = (const float4*)(g_MH + ((size_t)b*SEQ + q0)*EMB);
        #pragma unroll
        for (int i = 0; i < 4; ++i) {
            int idx = tid + i*256;                      // 0..1023
            float4 v = msrc[idx];
            ((float4*)(sMH + (idx >> 5)*132))[idx & 31] = v;
        }
    }

    const int q = tid >> 3;   // 0..31
    const int g = tid & 7;    // 0..7
    const float* Mrow = mask + ((size_t)b*SEQ + q0 + q)*SEQ;

    for (int nt = 0; nt < 8; ++nt) {
        const int n0 = nt * 64;
        __syncthreads();   // protect sShk (and cover first-iter sMH load)
        {
            const float4* ns = (const float4*)(nodes + ((size_t)b*SEQ + n0)*EMB);
            const float4* gs = (const float4*)(graph + ((size_t)b*SEQ + n0)*EMB);
            #pragma unroll
            for (int i = 0; i < 8; ++i) {
                int idx = tid + i*256;                  // 0..2047
                float4 a = ns[idx], c = gs[idx];
                a.x += c.x; a.y += c.y; a.z += c.z; a.w += c.w;
                ((float4*)(sShk + (idx >> 5)*132))[idx & 31] = a;
            }
        }
        __syncthreads();

        float acc[8];
        #pragma unroll
        for (int j = 0; j < 8; ++j) acc[j] = 0.f;
        const float4* mrow = (const float4*)(sMH + q*132);
        #pragma unroll 4
        for (int k4 = 0; k4 < 32; ++k4) {
            float4 m4 = mrow[k4];
            #pragma unroll
            for (int j = 0; j < 8; ++j) {
                float4 s4 = ((const float4*)(sShk + (g + 8*j)*132))[k4];
                acc[j] += m4.x*s4.x + m4.y*s4.y + m4.z*s4.z + m4.w*s4.w;
            }
        }
        #pragma unroll
        for (int j = 0; j < 8; ++j) {
            int n = n0 + g + 8*j;
            float val = 10.0f * tanhf(acc[j] * 0.088388347648318447f) + Mrow[n];
            sLg[q*516 + n] = val;
        }
    }
    __syncthreads();

    // phase 2: row softmax, coalesced writes
    const int wid = tid >> 5, lane = tid & 31;
    #pragma unroll
    for (int rr = 0; rr < 4; ++rr) {
        const int row = wid*4 + rr;
        const float* lrow = sLg + row*516;
        float vbuf[16];
        float mx = -1e30f;
        #pragma unroll
        for (int i = 0; i < 16; ++i) {
            float v = lrow[lane + 32*i];
            vbuf[i] = v;
            mx = fmaxf(mx, v);
        }
        #pragma unroll
        for (int off = 16; off > 0; off >>= 1)
            mx = fmaxf(mx, __shfl_xor_sync(0xffffffffu, mx, off));
        float ssum = 0.f;
        #pragma unroll
        for (int i = 0; i < 16; ++i) {
            float e = __expf(vbuf[i] - mx);
            vbuf[i] = e;
            ssum += e;
        }
        #pragma unroll
        for (int off = 16; off > 0; off >>= 1)
            ssum += __shfl_xor_sync(0xffffffffu, ssum, off);
        float inv = 1.0f / ssum;
        float* orow = out + ((size_t)b*SEQ + q0 + row)*SEQ;
        #pragma unroll
        for (int i = 0; i < 16; ++i)
            orow[lane + 32*i] = vbuf[i] * inv;
    }
}

// ---------------------------------------------------------------------------
// Launch
// ---------------------------------------------------------------------------
extern "C" void kernel_launch(void* const* d_in, const int* in_sizes, int n_in,
                              void* d_out, int out_size)
{
    const float* nodes = (const float*)d_in[0];
    const float* graph = (const float*)d_in[1];
    const float* q1    = (const float*)d_in[2];
    const float* fg    = (const float*)d_in[3];
    const float* ln    = (const float*)d_in[4];
    const float* lg    = (const float*)d_in[5];
    const float* mask  = (const float*)d_in[6];
    const float* Wqf   = (const float*)d_in[7];
    const float* Wql   = (const float*)d_in[8];
    const float* Wk    = (const float*)d_in[9];
    const float* Wv    = (const float*)d_in[10];
    const float* Wqfe  = (const float*)d_in[11];
    const float* Wqle  = (const float*)d_in[12];
    const float* Wke   = (const float*)d_in[13];
    const float* Wve   = (const float*)d_in[14];
    const float* Wc1   = (const float*)d_in[15];
    const float* bc1   = (const float*)d_in[16];
    const float* Wc2   = (const float*)d_in[17];
    const float* bc2   = (const float*)d_in[18];
    float* out = (float*)d_out;

    (void)in_sizes; (void)n_in; (void)out_size;

    cudaFuncSetAttribute(gemm128,      cudaFuncAttributeMaxDynamicSharedMemorySize, GEMM_SMEM);
    cudaFuncSetAttribute(attn_kernel,  cudaFuncAttributeMaxDynamicSharedMemorySize, ATTN_SMEM);
    cudaFuncSetAttribute(final_kernel, cudaFuncAttributeMaxDynamicSharedMemorySize, FINAL_SMEM);

    const int gemm_blocks = (NB*SEQ) / 64;   // 256

    // Q = q1@Wqf + ln@Wql + fg@Wqfe + lg@Wqle
    gemm128<<<gemm_blocks, 256, GEMM_SMEM>>>(JOB_Q, q1, ln, fg, lg,
                                             Wqf, Wql, Wqfe, Wqle, nullptr, nullptr);
    gemm128<<<gemm_blocks, 256, GEMM_SMEM>>>(JOB_K,  nodes, nullptr, nullptr, nullptr,
                                             Wk,  nullptr, nullptr, nullptr, nullptr, nullptr);
    gemm128<<<gemm_blocks, 256, GEMM_SMEM>>>(JOB_V,  nodes, nullptr, nullptr, nullptr,
                                             Wv,  nullptr, nullptr, nullptr, nullptr, nullptr);
    gemm128<<<gemm_blocks, 256, GEMM_SMEM>>>(JOB_KE, graph, nullptr, nullptr, nullptr,
                                             Wke, nullptr, nullptr, nullptr, nullptr, nullptr);
    gemm128<<<gemm_blocks, 256, GEMM_SMEM>>>(JOB_VE, graph, nullptr, nullptr, nullptr,
                                             Wve, nullptr, nullptr, nullptr, nullptr, nullptr);

    attn_kernel<<<dim3(8, 32, 2), 256, ATTN_SMEM>>>(mask);

    // MH = O1@Wc1 + O2@Wc2 + (bc1 + bc2)
    gemm128<<<gemm_blocks, 256, GEMM_SMEM>>>(JOB_MH, nullptr, nullptr, nullptr, nullptr,
                                             Wc1, Wc2, nullptr, nullptr, bc1, bc2);

    final_kernel<<<dim3(16, 32), 256, FINAL_SMEM>>>(nodes, graph, mask, out);
}